// round 2
// baseline (speedup 1.0000x reference)
#include <cuda_runtime.h>
#include <math.h>

// ---------------- problem constants ----------------
#define B_    64
#define TA    2048
#define FT    256
#define H_    1024
#define H4_   4096
#define CLS   96
#define EMB   256
#define TC    200

#define NCTA  128
#define NTHR  256

// smem row strides (floats) chosen for 16B alignment + low bank conflicts
#define US    1028      // U slice rows: 32 x 1028 floats
#define WS    260       // W slice rows: 32 x 260 floats

// smem layout (in floats)
#define SM_U    0
#define SM_W    (SM_U + 32 * US)                 // 32896
#define SM_HC   (SM_W + 32 * WS)                 // +8320
#define SM_Z    (SM_HC + 64 * 128)               // +8192
#define SM_MISC (SM_Z + 2048)                    // +2048
#define SM_FLOATS (SM_MISC + 64)
#define SMEM_BYTES (SM_FLOATS * 4)               // 206080 bytes

// ---------------- device globals (scratch; no allocation allowed) ----------------
__device__ float        g_h[2][B_ * H_];   // ping-pong hidden state
__device__ int          g_pred[B_];        // decoder feedback tokens
__device__ unsigned int g_bar = 0;         // monotonic grid barrier counter

// Monotonic-ticket grid barrier. Counter is always a multiple of NCTA between
// barrier episodes (every launch performs the same number of barriers with all
// NCTA CTAs), so it is safe across graph replays without any reset.
__device__ __forceinline__ void grid_sync_() {
    __threadfence();          // make this CTA's writes visible device-wide
    __syncthreads();
    if (threadIdx.x == 0) {
        unsigned int my   = atomicAdd(&g_bar, 1u);
        unsigned int goal = my - (my % NCTA) + NCTA;
        for (;;) {
            unsigned int v = *(volatile unsigned int*)&g_bar;
            if ((int)(v - goal) >= 0) break;
            __nanosleep(64);
        }
    }
    __threadfence();          // acquire: flush L1 so fresh h / preds are observed
    __syncthreads();
}

// acc[bi] += dot4 over a 128-wide K chunk.
// wrow = weight slice row for this thread's column (already offset by cc*stride + kbase)
// hc   = staged activations [64][128]
__device__ __forceinline__ void dot_chunk(const float* __restrict__ wrow,
                                          const float* __restrict__ hc,
                                          int b_base, float acc[8]) {
#pragma unroll 8
    for (int k = 0; k < 128; k += 4) {
        const float4 u = *reinterpret_cast<const float4*>(wrow + k);
#pragma unroll
        for (int bi = 0; bi < 8; ++bi) {
            const float4 h4 = *reinterpret_cast<const float4*>(hc + (b_base + bi) * 128 + k);
            acc[bi] = fmaf(u.x, h4.x, acc[bi]);
            acc[bi] = fmaf(u.y, h4.y, acc[bi]);
            acc[bi] = fmaf(u.z, h4.z, acc[bi]);
            acc[bi] = fmaf(u.w, h4.w, acc[bi]);
        }
    }
}

__device__ __forceinline__ float sigm_(float x) { return 1.0f / (1.0f + expf(-x)); }

__global__ void __launch_bounds__(NTHR, 1)
lstm_persistent(const float* __restrict__ x,
                const float* __restrict__ encW, const float* __restrict__ encU,
                const float* __restrict__ encb,
                const float* __restrict__ embed,
                const float* __restrict__ decW, const float* __restrict__ decU,
                const float* __restrict__ decb,
                const float* __restrict__ fcW, const float* __restrict__ fcb,
                const int* __restrict__ sotp,
                float* __restrict__ outf, int* __restrict__ outi, int mode)
{
    extern __shared__ float sm[];
    float* U_s = sm + SM_U;
    float* W_s = sm + SM_W;
    float* hc  = sm + SM_HC;    // staged activation chunk [64][128] (also emb / h-row scratch)
    float* z_s = sm + SM_Z;     // [4][512] gate pre-activations
    float* msc = sm + SM_MISC;

    const int tid    = threadIdx.x;
    const int cta    = blockIdx.x;
    const int cc     = tid & 31;           // which of this CTA's 32 columns
    const int b_base = (tid >> 5) * 8;     // 8 batch rows per thread
    const int gate   = cc >> 3;
    const int jl     = cc & 7;
    const int colg   = gate * H_ + cta * 8 + jl;   // global z column

    // ---- init: zero h0, load encoder weight slices into SMEM ----
    {
        const int base = cta * (B_ * H_ / NCTA);   // 512 floats per CTA
        for (int i = tid; i < B_ * H_ / NCTA; i += NTHR) g_h[0][base + i] = 0.0f;
    }
    for (int i = tid; i < 32 * FT; i += NTHR) {   // W_s[c][k] = encW[k][colg(c)]
        int c = i & 31, k = i >> 5;
        int cg = (c >> 3) * H_ + cta * 8 + (c & 7);
        W_s[c * WS + k] = encW[(size_t)k * H4_ + cg];
    }
    for (int i = tid; i < 32 * H_; i += NTHR) {   // U_s[c][k] = encU[k][colg(c)]
        int c = i & 31, k = i >> 5;
        int cg = (c >> 3) * H_ + cta * 8 + (c & 7);
        U_s[c * US + k] = encU[(size_t)k * H4_ + cg];
    }
    float bias = encb[colg];
    __syncthreads();
    grid_sync_();            // h0 zeros + everyone ready

    float c0r = 0.0f, c1r = 0.0f;   // cell state (thread owns pairs 2*tid, 2*tid+1)

    // =================== encoder: 2048 steps ===================
    for (int t = 0; t < TA; ++t) {
        const float* hbuf  = g_h[t & 1];
        float*       hnext = g_h[(t + 1) & 1];

        float acc[8];
#pragma unroll
        for (int i = 0; i < 8; ++i) acc[i] = 0.0f;

        // x_t contribution (K = 256, two 128-chunks)
#pragma unroll 1
        for (int kc = 0; kc < FT / 128; ++kc) {
            __syncthreads();
            for (int i = tid; i < 64 * 32; i += NTHR) {
                int b = i >> 5, k4 = (i & 31) << 2;
                *(float4*)&hc[b * 128 + k4] =
                    *(const float4*)&x[(size_t)b * (TA * FT) + (size_t)t * FT + kc * 128 + k4];
            }
            __syncthreads();
            dot_chunk(W_s + cc * WS + kc * 128, hc, b_base, acc);
        }
        // h contribution (K = 1024, eight 128-chunks)
#pragma unroll 1
        for (int kc = 0; kc < H_ / 128; ++kc) {
            __syncthreads();
            for (int i = tid; i < 64 * 32; i += NTHR) {
                int b = i >> 5, k4 = (i & 31) << 2;
                *(float4*)&hc[b * 128 + k4] = *(const float4*)&hbuf[b * H_ + kc * 128 + k4];
            }
            __syncthreads();
            dot_chunk(U_s + cc * US + kc * 128, hc, b_base, acc);
        }

        __syncthreads();
#pragma unroll
        for (int bi = 0; bi < 8; ++bi)
            z_s[gate * 512 + (b_base + bi) * 8 + jl] = acc[bi] + bias;
        __syncthreads();

        // gate math; each thread owns 2 (b, j) pairs
#pragma unroll
        for (int q = 0; q < 2; ++q) {
            int p = tid * 2 + q;
            float zi = z_s[p], zf = z_s[512 + p], zg = z_s[1024 + p], zo = z_s[1536 + p];
            float ig = sigm_(zi), fg = sigm_(zf), gg = tanhf(zg), og = sigm_(zo);
            float& cr = q ? c1r : c0r;
            cr = fg * cr + ig * gg;
            int b = p >> 3, j = p & 7;
            hnext[b * H_ + cta * 8 + j] = og * tanhf(cr);
        }
        grid_sync_();
    }

    // ---- swap weight slices to decoder ----
    for (int i = tid; i < 32 * EMB; i += NTHR) {
        int c = i & 31, k = i >> 5;
        int cg = (c >> 3) * H_ + cta * 8 + (c & 7);
        W_s[c * WS + k] = decW[(size_t)k * H4_ + cg];
    }
    for (int i = tid; i < 32 * H_; i += NTHR) {
        int c = i & 31, k = i >> 5;
        int cg = (c >> 3) * H_ + cta * 8 + (c & 7);
        U_s[c * US + k] = decU[(size_t)k * H4_ + cg];
    }
    bias = decb[colg];
    const int sotv = *sotp;
    __syncthreads();

    // =================== decoder: 200 steps ===================
    for (int s = 0; s < TC; ++s) {
        const float* hbuf  = g_h[s & 1];
        float*       hnext = g_h[(s + 1) & 1];

        float acc[8];
#pragma unroll
        for (int i = 0; i < 8; ++i) acc[i] = 0.0f;

        // embedding contribution (K = 256)
#pragma unroll 1
        for (int kc = 0; kc < EMB / 128; ++kc) {
            __syncthreads();
            for (int i = tid; i < 64 * 32; i += NTHR) {
                int b = i >> 5, k4 = (i & 31) << 2;
                int tok = (s == 0) ? sotv : g_pred[b];
                *(float4*)&hc[b * 128 + k4] =
                    *(const float4*)&embed[(size_t)tok * EMB + kc * 128 + k4];
            }
            __syncthreads();
            dot_chunk(W_s + cc * WS + kc * 128, hc, b_base, acc);
        }
        // h contribution (K = 1024)
#pragma unroll 1
        for (int kc = 0; kc < H_ / 128; ++kc) {
            __syncthreads();
            for (int i = tid; i < 64 * 32; i += NTHR) {
                int b = i >> 5, k4 = (i & 31) << 2;
                *(float4*)&hc[b * 128 + k4] = *(const float4*)&hbuf[b * H_ + kc * 128 + k4];
            }
            __syncthreads();
            dot_chunk(U_s + cc * US + kc * 128, hc, b_base, acc);
        }

        __syncthreads();
#pragma unroll
        for (int bi = 0; bi < 8; ++bi)
            z_s[gate * 512 + (b_base + bi) * 8 + jl] = acc[bi] + bias;
        __syncthreads();

#pragma unroll
        for (int q = 0; q < 2; ++q) {
            int p = tid * 2 + q;
            float zi = z_s[p], zf = z_s[512 + p], zg = z_s[1024 + p], zo = z_s[1536 + p];
            float ig = sigm_(zi), fg = sigm_(zf), gg = tanhf(zg), og = sigm_(zo);
            float& cr = q ? c1r : c0r;
            cr = fg * cr + ig * gg;
            int b = p >> 3, j = p & 7;
            hnext[b * H_ + cta * 8 + j] = og * tanhf(cr);
        }
        grid_sync_();   // h_new visible everywhere

        // ---- fc + softmax + argmax: CTA b handles batch row b ----
        if (cta < B_) {
            const int b = cta;
            for (int i = tid; i < H_ / 4; i += NTHR)
                *(float4*)&hc[i * 4] = *(const float4*)&hnext[b * H_ + i * 4];
            __syncthreads();
            if (tid < CLS) {
                float a0 = 0.f, a1 = 0.f, a2 = 0.f, a3 = 0.f;
#pragma unroll 4
                for (int k = 0; k < H_; k += 4) {
                    a0 = fmaf(hc[k + 0], __ldg(&fcW[(k + 0) * CLS + tid]), a0);
                    a1 = fmaf(hc[k + 1], __ldg(&fcW[(k + 1) * CLS + tid]), a1);
                    a2 = fmaf(hc[k + 2], __ldg(&fcW[(k + 2) * CLS + tid]), a2);
                    a3 = fmaf(hc[k + 3], __ldg(&fcW[(k + 3) * CLS + tid]), a3);
                }
                z_s[tid] = fcb[tid] + ((a0 + a1) + (a2 + a3));
            }
            __syncthreads();
            if (tid == 0) {
                float m = z_s[0];
                for (int j = 1; j < CLS; ++j) m = fmaxf(m, z_s[j]);
                float sum = 0.0f, best = -1.0f; int bi = 0;
                for (int j = 0; j < CLS; ++j) {
                    float e = expf(z_s[j] - m);
                    z_s[j] = e;
                    sum += e;
                    if (e > best) { best = e; bi = j; }   // first-max, matches jnp.argmax
                }
                msc[0] = sum;
                g_pred[b] = bi;
                if (mode == 0)      outf[(size_t)s * B_ + b] = (float)bi;
                else if (mode == 1) outi[(size_t)s * B_ + b] = bi;
            }
            __syncthreads();
            if (tid < CLS) {
                float pv = z_s[tid] / msc[0];
                if (mode == 0)
                    outf[(size_t)TC * B_ + ((size_t)s * B_ + b) * CLS + tid] = pv;
                else if (mode == 2)
                    outf[((size_t)s * B_ + b) * CLS + tid] = pv;
            }
        }
        grid_sync_();   // preds visible for next step's embedding
    }
}

extern "C" void kernel_launch(void* const* d_in, const int* in_sizes, int n_in,
                              void* d_out, int out_size) {
    const float* x    = (const float*)d_in[0];
    const float* encW = (const float*)d_in[1];
    const float* encU = (const float*)d_in[2];
    const float* encb = (const float*)d_in[3];
    const float* emb  = (const float*)d_in[4];
    const float* decW = (const float*)d_in[5];
    const float* decU = (const float*)d_in[6];
    const float* decb = (const float*)d_in[7];
    const float* fcW  = (const float*)d_in[8];
    const float* fcb  = (const float*)d_in[9];
    const int*   sot  = (const int*)d_in[10];

    // Output-layout handling: (preds, probs) tuple.
    int mode = 0;                                   // both, float32, preds first
    if (out_size == TC * B_)            mode = 1;   // preds only (int32)
    else if (out_size == TC * B_ * CLS) mode = 2;   // probs only (float32)

    cudaFuncSetAttribute(lstm_persistent,
                         cudaFuncAttributeMaxDynamicSharedMemorySize, SMEM_BYTES);

    lstm_persistent<<<NCTA, NTHR, SMEM_BYTES>>>(
        x, encW, encU, encb, emb, decW, decU, decb, fcW, fcb, sot,
        (float*)d_out, (int*)d_out, mode);
}